// round 7
// baseline (speedup 1.0000x reference)
#include <cuda_runtime.h>
#include <cuda_bf16.h>
#include <stdint.h>

// LearnablePeakExtractor:
//   thresh     = sigmoid(logit_thresh)
//   gate       = sigmoid(10*(x - thresh))
//   pooled[i]  = max(x[clamp(i-2)..clamp(i+2)])   (replicate pad == index clamp)
//   local_mask = sigmoid(10*(x - pooled))
//   smooth     = x * gate * local_mask
//   peak_mask  = smooth >= thresh
// Outputs concatenated: [smooth (N fp32), mask (N, as 0.0/1.0 fp32)].

#define ROW_L      131072
#define MD         2
#define TPB        256
#define VEC        4
#define TILE       (TPB * VEC)   // 1024 elements per block

__device__ __forceinline__ float fast_sigmoid(float z) {
    return 1.0f / (1.0f + __expf(-z));
}

__global__ __launch_bounds__(TPB, 8)
void peak_extract_kernel(const float* __restrict__ x,
                         const float* __restrict__ logit_thresh,
                         float* __restrict__ out_smooth,
                         float* __restrict__ out_mask,
                         int has_mask)
{
    __shared__ float s[TILE + 2 * MD];

    const int t         = threadIdx.x;
    const int row       = blockIdx.y;
    const long rowBase  = (long)row * ROW_L;
    const int tileStart = blockIdx.x * TILE;
    const float* xr     = x + rowBase;

    // ---- main tile load: fully coalesced float4 ----
    const int gIdx = tileStart + t * VEC;           // aligned by construction
    float4 v = *reinterpret_cast<const float4*>(xr + gIdx);
    s[MD + t * VEC + 0] = v.x;
    s[MD + t * VEC + 1] = v.y;
    s[MD + t * VEC + 2] = v.z;
    s[MD + t * VEC + 3] = v.w;

    // ---- halos (replicate-pad via clamp at row boundaries) ----
    if (t < MD) {
        int gl = tileStart - MD + t;                 // left halo
        gl = gl < 0 ? 0 : gl;
        s[t] = __ldg(xr + gl);
        int gr = tileStart + TILE + t;               // right halo
        gr = gr > (ROW_L - 1) ? (ROW_L - 1) : gr;
        s[MD + TILE + t] = __ldg(xr + gr);
    }
    __syncthreads();

    const float thr = fast_sigmoid(__ldg(logit_thresh));

    float4 sm, mk;
    const int base = MD + t * VEC;

    #pragma unroll
    for (int k = 0; k < VEC; ++k) {
        const float xv = s[base + k];
        float p = s[base + k - 2];
        p = fmaxf(p, s[base + k - 1]);
        p = fmaxf(p, xv);
        p = fmaxf(p, s[base + k + 1]);
        p = fmaxf(p, s[base + k + 2]);

        const float gate = fast_sigmoid(10.0f * (xv - thr));
        const float lm   = fast_sigmoid(10.0f * (xv - p));
        const float sp   = xv * gate * lm;

        ((float*)&sm)[k] = sp;
        ((float*)&mk)[k] = (sp >= thr) ? 1.0f : 0.0f;
    }

    const long oIdx = rowBase + gIdx;
    *reinterpret_cast<float4*>(out_smooth + oIdx) = sm;
    if (has_mask)
        *reinterpret_cast<float4*>(out_mask + oIdx) = mk;
}

extern "C" void kernel_launch(void* const* d_in, const int* in_sizes, int n_in,
                              void* d_out, int out_size)
{
    const float* peak_map = (const float*)d_in[0];
    const float* logit_th = (const float*)d_in[1];
    float* out = (float*)d_out;

    const long N = (long)in_sizes[0];          // B * L
    const int  B = (int)(N / ROW_L);
    const int  has_mask = (out_size >= 2 * N) ? 1 : 0;

    float* out_smooth = out;
    float* out_mask   = out + N;               // second plane (unused if !has_mask)

    dim3 grid(ROW_L / TILE, B, 1);             // 128 x 256
    peak_extract_kernel<<<grid, TPB>>>(peak_map, logit_th,
                                       out_smooth, out_mask, has_mask);
}

// round 8
// speedup vs baseline: 1.1487x; 1.1487x over previous
#include <cuda_runtime.h>
#include <cuda_bf16.h>
#include <stdint.h>

// LearnablePeakExtractor:
//   thresh     = sigmoid(logit_thresh)
//   gate       = sigmoid(10*(x - thresh))
//   pooled[i]  = max(x[clamp(i-2)..clamp(i+2)])   (replicate pad == index clamp)
//   local_mask = sigmoid(10*(x - pooled))
//   smooth     = x * gate * local_mask
//   peak_mask  = smooth >= thresh
// Key algebra: gate*local_mask = 1 / ((1+e^-a)(1+e^-b))  -> 2x EX2 + 1x RCP.
// Outputs concatenated: [smooth (N fp32), mask (N, as 0.0/1.0 fp32)].

#define ROW_L      131072
#define TPB        256
#define VEC        8
#define TILE       (TPB * VEC)   // 2048 elements per block, 64 tiles/row

__device__ float g_thresh;

__global__ void compute_thresh_kernel(const float* __restrict__ logit_thresh)
{
    g_thresh = 1.0f / (1.0f + __expf(-logit_thresh[0]));
}

__global__ __launch_bounds__(TPB, 8)
void peak_extract_kernel(const float* __restrict__ x,
                         float* __restrict__ out_smooth,
                         float* __restrict__ out_mask,
                         int has_mask)
{
    const int  t        = threadIdx.x;
    const int  row      = blockIdx.y;
    const long rowBase  = (long)row * ROW_L;
    const int  i        = blockIdx.x * TILE + t * VEC;   // multiple of 8
    const float* xr     = x + rowBase;

    // ---- gather window [i-2 .. i+9] into registers (12 floats) ----
    // All sub-loads naturally aligned: i%8==0 -> (i-2) is 8B-aligned, i is 32B-aligned.
    float w[VEC + 4];

    float2 a;
    if (i >= 2) {
        a = *reinterpret_cast<const float2*>(xr + i - 2);
    } else {                      // i == 0: replicate-pad left
        a.x = xr[0]; a.y = xr[0];
    }
    float4 b = *reinterpret_cast<const float4*>(xr + i);
    float4 c = *reinterpret_cast<const float4*>(xr + i + 4);
    float2 d;
    if (i + 9 <= ROW_L - 1) {
        d = *reinterpret_cast<const float2*>(xr + i + 8);
    } else {                      // i == ROW_L-8: replicate-pad right
        d.x = xr[ROW_L - 1]; d.y = xr[ROW_L - 1];
    }

    w[0] = a.x;  w[1] = a.y;
    w[2] = b.x;  w[3] = b.y;  w[4]  = b.z;  w[5]  = b.w;
    w[6] = c.x;  w[7] = c.y;  w[8]  = c.z;  w[9]  = c.w;
    w[10] = d.x; w[11] = d.y;

    // ---- pairwise maxes for the 5-wide sliding window ----
    float m[VEC + 3];
    #pragma unroll
    for (int j = 0; j < VEC + 3; ++j)
        m[j] = fmaxf(w[j], w[j + 1]);

    const float thr = g_thresh;

    float4 sm0, sm1, mk0, mk1;
    float* smp = (float*)&sm0;    // sm0/sm1 contiguous in regs via indexing below
    float* mkp = (float*)&mk0;

    float sres[VEC], mres[VEC];
    #pragma unroll
    for (int k = 0; k < VEC; ++k) {
        const float xv = w[k + 2];
        const float p  = fmaxf(fmaxf(m[k], m[k + 2]), w[k + 4]);

        // ea = e^{-10(xv-thr)}, eb = e^{-10(xv-p)}
        const float ea = __expf(10.0f * (thr - xv));
        const float eb = __expf(10.0f * (p   - xv));
        const float denom = (1.0f + ea) * (1.0f + eb);
        const float sp = __fdividef(xv, denom);   // xv * gate * local_mask

        sres[k] = sp;
        mres[k] = (sp >= thr) ? 1.0f : 0.0f;
    }
    (void)smp; (void)mkp;

    sm0 = make_float4(sres[0], sres[1], sres[2], sres[3]);
    sm1 = make_float4(sres[4], sres[5], sres[6], sres[7]);
    mk0 = make_float4(mres[0], mres[1], mres[2], mres[3]);
    mk1 = make_float4(mres[4], mres[5], mres[6], mres[7]);

    const long o = rowBase + i;
    *reinterpret_cast<float4*>(out_smooth + o)     = sm0;
    *reinterpret_cast<float4*>(out_smooth + o + 4) = sm1;
    if (has_mask) {
        *reinterpret_cast<float4*>(out_mask + o)     = mk0;
        *reinterpret_cast<float4*>(out_mask + o + 4) = mk1;
    }
}

extern "C" void kernel_launch(void* const* d_in, const int* in_sizes, int n_in,
                              void* d_out, int out_size)
{
    const float* peak_map = (const float*)d_in[0];
    const float* logit_th = (const float*)d_in[1];
    float* out = (float*)d_out;

    const long N = (long)in_sizes[0];          // B * L
    const int  B = (int)(N / ROW_L);
    const int  has_mask = (out_size >= 2 * N) ? 1 : 0;

    float* out_smooth = out;
    float* out_mask   = out + N;

    compute_thresh_kernel<<<1, 1>>>(logit_th);

    dim3 grid(ROW_L / TILE, B, 1);             // 64 x 256
    peak_extract_kernel<<<grid, TPB>>>(peak_map, out_smooth, out_mask, has_mask);
}

// round 10
// speedup vs baseline: 1.1856x; 1.0321x over previous
#include <cuda_runtime.h>
#include <cuda_bf16.h>
#include <stdint.h>

// LearnablePeakExtractor:
//   thresh     = sigmoid(logit_thresh)
//   gate       = sigmoid(10*(x - thresh))
//   pooled[i]  = max(x[clamp(i-2)..clamp(i+2)])   (replicate pad == index clamp)
//   local_mask = sigmoid(10*(x - pooled))
//   smooth     = x * gate * local_mask
//   peak_mask  = smooth >= thresh
// Algebra: gate*local_mask = 1/((1+e^-a)(1+e^-b)) -> 2x EX2 + 1 divide.
// All loads/stores use streaming (.cs) cache hints: data is single-use, keep L2
// free for the read/write streams instead of allocating 256MB of write-once data.
// Outputs concatenated: [smooth (N fp32), mask (N, as 0.0/1.0 fp32)].

#define ROW_L      131072
#define TPB        256
#define VEC        8
#define TILE       (TPB * VEC)   // 2048 elements per block, 64 tiles/row

__device__ float g_thresh;

__global__ void compute_thresh_kernel(const float* __restrict__ logit_thresh)
{
    g_thresh = 1.0f / (1.0f + __expf(-logit_thresh[0]));
}

__global__ __launch_bounds__(TPB, 8)
void peak_extract_kernel(const float* __restrict__ x,
                         float* __restrict__ out_smooth,
                         float* __restrict__ out_mask,
                         int has_mask)
{
    const int  t        = threadIdx.x;
    const int  row      = blockIdx.y;
    const long rowBase  = (long)row * ROW_L;
    const int  i        = blockIdx.x * TILE + t * VEC;   // multiple of 8
    const float* xr     = x + rowBase;

    // ---- gather window [i-2 .. i+9] into registers (12 floats), branch-free ----
    // Clamped addresses stay 8B-aligned; value fix-ups are register selects.
    const int li = (i >= 2) ? (i - 2) : 0;               // == max(i-2, 0)
    const int ri = (i + 8 <= ROW_L - 2) ? (i + 8) : (ROW_L - 2);

    float2 a = __ldcs(reinterpret_cast<const float2*>(xr + li));
    float4 b = __ldcs(reinterpret_cast<const float4*>(xr + i));
    float4 c = __ldcs(reinterpret_cast<const float4*>(xr + i + 4));
    float2 d = __ldcs(reinterpret_cast<const float2*>(xr + ri));

    // i==0: loaded (x0,x1), need (x0,x0). i==L-8: loaded (x[L-2],x[L-1]), need (x[L-1],x[L-1]).
    if (i == 0)           a.y = a.x;
    if (i == ROW_L - VEC) d.x = d.y;

    float w[VEC + 4];
    w[0]  = a.x; w[1]  = a.y;
    w[2]  = b.x; w[3]  = b.y; w[4]  = b.z; w[5]  = b.w;
    w[6]  = c.x; w[7]  = c.y; w[8]  = c.z; w[9]  = c.w;
    w[10] = d.x; w[11] = d.y;

    // ---- pairwise maxes for the 5-wide sliding window ----
    float m[VEC + 3];
    #pragma unroll
    for (int j = 0; j < VEC + 3; ++j)
        m[j] = fmaxf(w[j], w[j + 1]);

    const float thr = g_thresh;

    float sres[VEC], mres[VEC];
    #pragma unroll
    for (int k = 0; k < VEC; ++k) {
        const float xv = w[k + 2];
        const float p  = fmaxf(fmaxf(m[k], m[k + 2]), w[k + 4]);

        const float ea = __expf(10.0f * (thr - xv));   // e^{-10(xv-thr)}
        const float eb = __expf(10.0f * (p   - xv));   // e^{-10(xv-p)}
        const float denom = (1.0f + ea) * (1.0f + eb);
        const float sp = __fdividef(xv, denom);        // xv * gate * local_mask

        sres[k] = sp;
        mres[k] = (sp >= thr) ? 1.0f : 0.0f;
    }

    const float4 sm0 = make_float4(sres[0], sres[1], sres[2], sres[3]);
    const float4 sm1 = make_float4(sres[4], sres[5], sres[6], sres[7]);
    const float4 mk0 = make_float4(mres[0], mres[1], mres[2], mres[3]);
    const float4 mk1 = make_float4(mres[4], mres[5], mres[6], mres[7]);

    const long o = rowBase + i;
    __stcs(reinterpret_cast<float4*>(out_smooth + o),     sm0);
    __stcs(reinterpret_cast<float4*>(out_smooth + o + 4), sm1);
    if (has_mask) {
        __stcs(reinterpret_cast<float4*>(out_mask + o),     mk0);
        __stcs(reinterpret_cast<float4*>(out_mask + o + 4), mk1);
    }
}

extern "C" void kernel_launch(void* const* d_in, const int* in_sizes, int n_in,
                              void* d_out, int out_size)
{
    const float* peak_map = (const float*)d_in[0];
    const float* logit_th = (const float*)d_in[1];
    float* out = (float*)d_out;

    const long N = (long)in_sizes[0];          // B * L
    const int  B = (int)(N / ROW_L);
    const int  has_mask = (out_size >= 2 * N) ? 1 : 0;

    float* out_smooth = out;
    float* out_mask   = out + N;

    compute_thresh_kernel<<<1, 1>>>(logit_th);

    dim3 grid(ROW_L / TILE, B, 1);             // 64 x 256
    peak_extract_kernel<<<grid, TPB>>>(peak_map, out_smooth, out_mask, has_mask);
}